// round 7
// baseline (speedup 1.0000x reference)
#include <cuda_runtime.h>
#include <cuda_bf16.h>
#include <cstdint>

// PatchEmbeder via mma.sync bf16 (split hi/lo) + affine collapse.
// out[b,0,:]   = cls + pos[0]                                  (prep kernel)
// out[b,p+1,:] = x_patch @ W1 @ (W2@W3) + beff + pos[p+1]      (main kernel)
// x[b,p,k] = inputs[b, k/256, p, (k%256)/16, k%16]
// B=128, P=196 -> 25088 rows = 784 CTAs x 32 rows. K1=768, N1=32(=K2), E=768.
//
// R7: occupancy attack. 784 CTAs x 4 warps (warp pairs share 16 rows:
// split-K in G1 with smem reduce, split-N in G23). Warp-private staging,
// no CTA barriers in G1.

#define THREADS 128

// ---- device scratch (rebuilt every replay by prep_kernel) ----
// Fragment-layout weights for mma.sync m16n8k16 (B operand, col-major frag):
//   uint4 per (fragment, lane): {b0_hi, b1_hi, b0_lo, b1_lo}
__device__ __align__(16) uint4 g_W1F [6 * 8 * 4 * 32];  // [k-tile 48][n-tile 4][lane]
__device__ __align__(16) uint4 g_W23F[96 * 2 * 32];     // [n-tile 96][k-tile 2][lane]
__device__ __align__(16) float g_beff[768];

__device__ __forceinline__ uint32_t bf2bits(__nv_bfloat162 v) {
    return *reinterpret_cast<uint32_t*>(&v);
}
__device__ __forceinline__ void split2(float a, float b, uint32_t& h, uint32_t& l) {
    __nv_bfloat162 H = __floats2bfloat162_rn(a, b);
    float ha = __bfloat162float(H.x), hb = __bfloat162float(H.y);
    __nv_bfloat162 L = __floats2bfloat162_rn(a - ha, b - hb);
    h = bf2bits(H); l = bf2bits(L);
}

__device__ __forceinline__ void mma16816(float& c0, float& c1, float& c2, float& c3,
                                         const uint32_t a[4], uint32_t b0, uint32_t b1) {
    asm("mma.sync.aligned.m16n8k16.row.col.f32.bf16.bf16.f32 "
        "{%0,%1,%2,%3}, {%4,%5,%6,%7}, {%8,%9}, {%0,%1,%2,%3};"
        : "+f"(c0), "+f"(c1), "+f"(c2), "+f"(c3)
        : "r"(a[0]), "r"(a[1]), "r"(a[2]), "r"(a[3]), "r"(b0), "r"(b1));
}
__device__ __forceinline__ void ldsm4(uint32_t r[4], uint32_t addr) {
    asm volatile("ldmatrix.sync.aligned.m8n8.x4.shared.b16 {%0,%1,%2,%3}, [%4];"
                 : "=r"(r[0]), "=r"(r[1]), "=r"(r[2]), "=r"(r[3]) : "r"(addr));
}
__device__ __forceinline__ uint32_t smem_u32(const void* p) {
    uint32_t a;
    asm("{ .reg .u64 t; cvta.to.shared.u64 t, %1; cvt.u32.u64 %0, t; }" : "=r"(a) : "l"(p));
    return a;
}

// =====================================================================
// prep: bake W1 / W23=W2@W3 fragments (hi/lo), beff, cls rows.
// grid 96 x 256 = 24576 threads. W2 staged in smem (stride 65), t1[j]
// computed once per block; beff folded into the W23 loop.
// =====================================================================
__global__ void prep_kernel(const float* __restrict__ W1, const float* __restrict__ b1,
                            const float* __restrict__ W2, const float* __restrict__ b2,
                            const float* __restrict__ W3, const float* __restrict__ b3,
                            const float* __restrict__ cls, const float* __restrict__ pos,
                            float* __restrict__ out)
{
    __shared__ float W2s[32 * 65];   // padded stride 65
    __shared__ float t1s[64];

    const int t = threadIdx.x;
    const int g = blockIdx.x * 256 + t;   // 0..24575

#pragma unroll
    for (int i = t; i < 2048; i += 256)
        W2s[(i >> 6) * 65 + (i & 63)] = __ldg(W2 + i);
    __syncthreads();

    if (t < 64) {
        float acc = __ldg(b2 + t);
#pragma unroll
        for (int i = 0; i < 32; ++i) acc += __ldg(b1 + i) * W2s[i * 65 + t];
        t1s[t] = acc;
    }
    __syncthreads();

    // ---- W1 fragments: element (k = g>>5 in 0..767, n = g&31) ----
    {
        const int k = g >> 5, n = g & 31;
        const float v = __ldg(W1 + k * 32 + n);
        const __nv_bfloat16 h = __float2bfloat16(v);
        const __nv_bfloat16 l = __float2bfloat16(v - __bfloat162float(h));
        const int kt = k >> 4, kin = k & 15;
        const int lane = ((n & 7) << 2) + ((kin & 7) >> 1);
        const int reg = kin >> 3, half = kin & 1;
        uint16_t* base = (uint16_t*)&g_W1F[((kt << 2) + (n >> 3)) * 32 + lane];
        base[(reg << 1) + half]     = *(const uint16_t*)&h;
        base[4 + (reg << 1) + half] = *(const uint16_t*)&l;
    }
    // ---- W23 fragments + beff: (e = g>>5, k2 = g&31) ----
    {
        const int e = g >> 5, k2 = g & 31;
        float acc = 0.f;
        float accb = (k2 == 0) ? __ldg(b3 + e) : 0.f;
#pragma unroll
        for (int j = 0; j < 64; ++j) {
            const float w3v = __ldg(W3 + j * 768 + e);   // warp-uniform broadcast
            acc += W2s[k2 * 65 + j] * w3v;
            if (k2 == 0) accb += t1s[j] * w3v;
        }
        const __nv_bfloat16 h = __float2bfloat16(acc);
        const __nv_bfloat16 l = __float2bfloat16(acc - __bfloat162float(h));
        const int kt = k2 >> 4, kin = k2 & 15;
        const int lane = ((e & 7) << 2) + ((kin & 7) >> 1);
        const int reg = kin >> 3, half = kin & 1;
        uint16_t* base = (uint16_t*)&g_W23F[(((e >> 3) << 1) + kt) * 32 + lane];
        base[(reg << 1) + half]     = *(const uint16_t*)&h;
        base[4 + (reg << 1) + half] = *(const uint16_t*)&l;
        if (k2 == 0) g_beff[e] = accb;
    }
    // ---- cls rows: out[b][0][:] = cls + pos[0]  (128 b x 192 float4) ----
    {
        const int e4 = g % 192, b = g / 192;
        const float4 c = __ldg((const float4*)cls + e4);
        const float4 pp = __ldg((const float4*)pos + e4);
        *((float4*)(out + (size_t)b * 197 * 768) + e4) =
            make_float4(c.x + pp.x, c.y + pp.y, c.z + pp.z, c.w + pp.w);
    }
}

// =====================================================================
// main: 784 CTAs x 128 threads (4 warps), 32 rows each.
// Warp pair (w, w^1) owns 16 rows: rowgrp = w>>1, ksel/ntsel = w&1.
// smem: 4 x 8 KB warp-private staging + 8 KB reduce buffer = 40 KB.
// Staging row layout: local row lr at lr*512: [hi 256B | lo 256B],
// 16B groups swizzled by g' = g ^ (lr&7) for conflict-free ldmatrix.
// =====================================================================
__global__ __launch_bounds__(THREADS, 4)
void patch_embed_mma(const float* __restrict__ X, const float* __restrict__ pos,
                     float* __restrict__ out)
{
    extern __shared__ char smem[];
    const uint32_t sb = smem_u32(smem);
    const int t = threadIdx.x;
    const int w = t >> 5;               // 4 warps
    const int ln = t & 31;
    const int r0 = blockIdx.x * 32;
    const int rowgrp = w >> 1;          // 0: rows 0-15, 1: rows 16-31
    const int ksel = w & 1;             // 0: K-chunks 0-2, 1: chunks 3-5
    const int wr0 = rowgrp << 4;
    const uint32_t wbase = sb + (uint32_t)w * 8192;
    float* const redbuf = (float*)(smem + 32768);   // [4][32][16] fp32

    // ---------------- G1 (split-K): partial H[16x32] over 3 K-chunks --------------
    float acc1[4][4];
#pragma unroll
    for (int i = 0; i < 4; ++i)
#pragma unroll
        for (int j = 0; j < 4; ++j) acc1[i][j] = 0.f;

    const int m  = ln >> 3;                          // ldmatrix matrix index 0..3
    const int rrl = (ln & 7) + ((m & 1) << 3);       // local row this lane points at
    const uint32_t lane_rowbase = wbase + rrl * 512;
    const int ggm = m >> 1;                          // k low/high 8 group

    const int kk  = ln << 2;                         // lane's 4 k-values in chunk
    const int gsw = ln >> 1;                         // 16B group = k/8
    const int off8 = (ln & 1) << 3;

    for (int c = 0; c < 3; ++c) {
        const int kc = ksel * 3 + c;
        if (c) __syncwarp();
        // ---- stage 16 rows x 128 k (channel kc/2, rem (kc&1)*128), warp-private ----
        const int ch = kc >> 1;
        const int rem0 = (kc & 1) << 7;
#pragma unroll
        for (int lr = 0; lr < 16; ++lr) {
            const int R = r0 + wr0 + lr;
            const int b = R / 196;
            const int p = R - b * 196;
            const float4 v = __ldg((const float4*)(
                X + (((size_t)(b * 3 + ch) * 196 + p) << 8) + rem0 + kk));
            __nv_bfloat162 h01 = __floats2bfloat162_rn(v.x, v.y);
            __nv_bfloat162 h23 = __floats2bfloat162_rn(v.z, v.w);
            __nv_bfloat162 l01 = __floats2bfloat162_rn(v.x - __bfloat162float(h01.x),
                                                       v.y - __bfloat162float(h01.y));
            __nv_bfloat162 l23 = __floats2bfloat162_rn(v.z - __bfloat162float(h23.x),
                                                       v.w - __bfloat162float(h23.y));
            const uint32_t base = (uint32_t)lr * 512 + ((uint32_t)(gsw ^ (lr & 7)) << 4) + off8;
            *(uint2*)(smem + (wbase - sb) + base)       = make_uint2(bf2bits(h01), bf2bits(h23));
            *(uint2*)(smem + (wbase - sb) + base + 256) = make_uint2(bf2bits(l01), bf2bits(l23));
        }
        __syncwarp();

        // ---- consume: 8 k-tiles of 16 ----
#pragma unroll
        for (int kt = 0; kt < 8; ++kt) {
            const int gg = (kt << 1) + ggm;
            const uint32_t ahaddr = lane_rowbase + ((uint32_t)(gg ^ (rrl & 7)) << 4);
            uint32_t ah[4], al[4];
            ldsm4(ah, ahaddr);
            ldsm4(al, ahaddr + 256);
            const uint4* bp = &g_W1F[(((kc << 3) + kt) << 2) * 32 + ln];
            uint4 bf[4];
#pragma unroll
            for (int nt = 0; nt < 4; ++nt) bf[nt] = __ldg(bp + nt * 32);
#pragma unroll
            for (int nt = 0; nt < 4; ++nt)
                mma16816(acc1[nt][0], acc1[nt][1], acc1[nt][2], acc1[nt][3], ah, bf[nt].x, bf[nt].y);
#pragma unroll
            for (int nt = 0; nt < 4; ++nt)
                mma16816(acc1[nt][0], acc1[nt][1], acc1[nt][2], acc1[nt][3], al, bf[nt].x, bf[nt].y);
#pragma unroll
            for (int nt = 0; nt < 4; ++nt)
                mma16816(acc1[nt][0], acc1[nt][1], acc1[nt][2], acc1[nt][3], ah, bf[nt].z, bf[nt].w);
        }
    }

    // ---------------- reduce partial H across warp pair (w, w^1) -------------------
    {
        float4* dst = (float4*)&redbuf[(w * 32 + ln) * 16];
#pragma unroll
        for (int i = 0; i < 4; ++i)
            dst[i] = make_float4(acc1[i][0], acc1[i][1], acc1[i][2], acc1[i][3]);
    }
    __syncthreads();
    {
        const float4* src = (const float4*)&redbuf[((w ^ 1) * 32 + ln) * 16];
#pragma unroll
        for (int i = 0; i < 4; ++i) {
            const float4 v = src[i];
            acc1[i][0] += v.x; acc1[i][1] += v.y; acc1[i][2] += v.z; acc1[i][3] += v.w;
        }
    }

    // ---------------- H fragments -> G23 A fragments (thread-local remap) ----------
    uint32_t Ah[2][4], Al[2][4];
#pragma unroll
    for (int q = 0; q < 2; ++q) {
        split2(acc1[2*q][0],   acc1[2*q][1],   Ah[q][0], Al[q][0]);
        split2(acc1[2*q][2],   acc1[2*q][3],   Ah[q][1], Al[q][1]);
        split2(acc1[2*q+1][0], acc1[2*q+1][1], Ah[q][2], Al[q][2]);
        split2(acc1[2*q+1][2], acc1[2*q+1][3], Ah[q][3], Al[q][3]);
    }

    // ---------------- G23 (split-N): this warp does 48 of 96 n-tiles ---------------
    const int rA = r0 + wr0 + (ln >> 2);
    const int bA = rA / 196, pA = rA - bA * 196;
    const int rB = rA + 8;
    const int bB = rB / 196, pB = rB - bB * 196;
    float* const orowA = out + ((size_t)bA * 197 + pA + 1) * 768;
    float* const orowB = out + ((size_t)bB * 197 + pB + 1) * 768;
    const float* const prowA = pos + (pA + 1) * 768;
    const float* const prowB = pos + (pB + 1) * 768;
    const int ncol = (ln & 3) << 1;
    const int nt0 = (w & 1) * 48;

#pragma unroll 4
    for (int i = 0; i < 48; ++i) {
        const int nt = nt0 + i;
        const uint4 b0 = __ldg(&g_W23F[((nt << 1) + 0) * 32 + ln]);
        const uint4 b1 = __ldg(&g_W23F[((nt << 1) + 1) * 32 + ln]);
        float h0 = 0.f, h1 = 0.f, h2 = 0.f, h3 = 0.f;   // Ah*Bh
        float g0 = 0.f, g1 = 0.f, g2 = 0.f, g3 = 0.f;   // Ah*Bl
        float l0 = 0.f, l1 = 0.f, l2 = 0.f, l3 = 0.f;   // Al*Bh
        mma16816(h0, h1, h2, h3, Ah[0], b0.x, b0.y);
        mma16816(g0, g1, g2, g3, Ah[0], b0.z, b0.w);
        mma16816(l0, l1, l2, l3, Al[0], b0.x, b0.y);
        mma16816(h0, h1, h2, h3, Ah[1], b1.x, b1.y);
        mma16816(g0, g1, g2, g3, Ah[1], b1.z, b1.w);
        mma16816(l0, l1, l2, l3, Al[1], b1.x, b1.y);

        const int n = (nt << 3) + ncol;
        const float2 be = __ldg((const float2*)(g_beff + n));
        const float2 pa = __ldg((const float2*)(prowA + n));
        const float2 pb = __ldg((const float2*)(prowB + n));
        *(float2*)(orowA + n) = make_float2((h0 + g0) + (l0 + be.x + pa.x),
                                            (h1 + g1) + (l1 + be.y + pa.y));
        *(float2*)(orowB + n) = make_float2((h2 + g2) + (l2 + be.x + pb.x),
                                            (h3 + g3) + (l3 + be.y + pb.y));
    }
}

extern "C" void kernel_launch(void* const* d_in, const int* in_sizes, int n_in,
                              void* d_out, int out_size)
{
    const float* X   = (const float*)d_in[0];
    const float* W1  = (const float*)d_in[1];
    const float* b1  = (const float*)d_in[2];
    const float* W2  = (const float*)d_in[3];
    const float* b2  = (const float*)d_in[4];
    const float* W3  = (const float*)d_in[5];
    const float* b3  = (const float*)d_in[6];
    const float* cls = (const float*)d_in[7];
    const float* pos = (const float*)d_in[8];
    float* out = (float*)d_out;

    const int smem = 40960;   // 4 x 8 KB staging + 8 KB reduce
    cudaFuncSetAttribute(patch_embed_mma,
                         cudaFuncAttributeMaxDynamicSharedMemorySize, smem);

    prep_kernel<<<96, 256>>>(W1, b1, W2, b2, W3, b3, cls, pos, out);
    patch_embed_mma<<<784, THREADS, smem>>>(X, pos, out);
}